// round 16
// baseline (speedup 1.0000x reference)
#include <cuda_runtime.h>
#include <cuda_fp16.h>
#include <math.h>
#include <stdint.h>

#define BMAX 16384

__device__ __forceinline__ unsigned long long ffma2(unsigned long long a,
                                                    unsigned long long b,
                                                    unsigned long long c) {
    unsigned long long d;
    asm("fma.rn.f32x2 %0, %1, %2, %3;" : "=l"(d) : "l"(a), "l"(b), "l"(c));
    return d;
}
__device__ __forceinline__ void unpack2(unsigned long long v, float& lo, float& hi) {
    asm("mov.b64 {%0, %1}, %2;" : "=f"(lo), "=f"(hi) : "l"(v));
}
__device__ __forceinline__ uint32_t smem_u32(const void* p) {
    uint32_t a;
    asm("{ .reg .u64 t; cvta.to.shared.u64 t, %1; cvt.u32.u64 %0, t; }" : "=r"(a) : "l"(p));
    return a;
}
__device__ __forceinline__ void ldsm4t(uint32_t& r0, uint32_t& r1, uint32_t& r2,
                                       uint32_t& r3, uint32_t addr) {
    asm volatile("ldmatrix.sync.aligned.m8n8.x4.trans.shared.b16 {%0,%1,%2,%3}, [%4];"
                 : "=r"(r0), "=r"(r1), "=r"(r2), "=r"(r3) : "r"(addr));
}
__device__ __forceinline__ void mma_f16(float* c, uint32_t a0, uint32_t a1,
                                        uint32_t a2, uint32_t a3,
                                        uint32_t b0, uint32_t b1) {
    asm volatile("mma.sync.aligned.m16n8k16.row.col.f32.f16.f16.f32 "
                 "{%0,%1,%2,%3}, {%4,%5,%6,%7}, {%8,%9}, {%0,%1,%2,%3};"
                 : "+f"(c[0]), "+f"(c[1]), "+f"(c[2]), "+f"(c[3])
                 : "r"(a0), "r"(a1), "r"(a2), "r"(a3), "r"(b0), "r"(b1));
}

__device__ float g_xT[480 * BMAX];
__device__ float g_cg[615];
__device__ __half g_w[3][28672];   // fp16 W, [(c16*N+v)*16+kk], norm folded

__constant__ int C_np[3]     = {3,6,6};
__constant__ int C_d1[3][6]  = {{1,3,5,0,0,0},{1,3,3,3,5,5},{1,3,3,5,5,5}};
__constant__ int C_d2[3][6]  = {{1,3,5,0,0,0},{3,1,3,5,3,5},{5,3,5,1,3,5}};
__constant__ int C_xb[3][6]  = {{0,128,320,0,0,0},{0,128,128,128,320,320},{0,128,128,320,320,320}};
__constant__ int C_yo[3][6]  = {{0,1,4,0,0,0},{1,0,1,4,1,4},{4,1,4,0,1,4}};
__constant__ int C_cgo[3][6] = {{0,1,10,0,0,0},{35,44,53,80,125,170},{245,270,315,390,415,490}};
__constant__ int C_uo[3][6]  = {{0,128,192,0,0,0},{0,128,192,256,320,352},{0,128,192,256,288,320}};
__constant__ int C_ao[3][6]  = {{0,1,4,0,0,0},{0,3,12,21,30,45},{0,5,20,35,60,85}};

// ===== host-side CG (exact reference algorithm) =====
namespace hostcg {
struct cpx { double re, im; };
static inline cpx cmul(cpx a, cpx b) { return { a.re*b.re - a.im*b.im, a.re*b.im + a.im*b.re }; }
static const double F[9] = {1.,1.,2.,6.,24.,120.,720.,5040.,40320.};
static double su2(int j1,int j2,int j3,int m1,int m2) {
    int m3 = m1 + m2;
    double pref = sqrt((2.0*j3+1.0)*F[j1+j2-j3]*F[j1-j2+j3]*F[-j1+j2+j3]/F[j1+j2+j3+1]);
    pref *= sqrt(F[j3+m3]*F[j3-m3]*F[j1-m1]*F[j1+m1]*F[j2-m2]*F[j2+m2]);
    double s = 0.0;
    for (int v = 0; v <= j1+j2-j3; v++) {
        int a=j1+j2-j3-v, b=j1-m1-v, c=j2+m2-v, d=j3-j2+m1+v, e=j3-j1-m2+v;
        if (a<0||b<0||c<0||d<0||e<0) continue;
        double t = 1.0/(F[v]*F[a]*F[b]*F[c]*F[d]*F[e]);
        s += (v & 1) ? -t : t;
    }
    return pref * s;
}
static cpx Qe(int l, int row, int col) {
    const double R = 0.70710678118654752440;
    cpx q = {0.0, 0.0};
    int m = row - l;
    if (m < 0)      { if (col == 2*l-row) q.re = R; else if (col == row) q.im = -R; }
    else if (m == 0){ if (col == l) q.re = 1.0; }
    else { double s = (m&1)?-1.0:1.0;
           if (col == row) q.re = s*R; else if (col == 2*l-row) q.im = s*R; }
    if (l == 1)      { double t = q.re; q.re = q.im; q.im = -t; }
    else if (l == 2) { q.re = -q.re; q.im = -q.im; }
    return q;
}
static void compute(float* o) {
    static const int P1[15]={0,1,2,0,1,1,1,2,2,0,1,1,2,2,2};
    static const int P2[15]={0,1,2,1,0,1,2,1,2,2,1,2,0,1,2};
    static const int P3[15]={0,0,0,1,1,1,1,1,1,2,2,2,2,2,2};
    static const int PO[15]={0,1,10,35,44,53,80,125,170,245,270,315,390,415,490};
    for (int p = 0; p < 15; p++) {
        int l1=P1[p], l2=P2[p], l3=P3[p], d1=2*l1+1, d2=2*l2+1, d3=2*l3+1;
        for (int e = 0; e < d1*d2*d3; e++) {
            int m=e%d3, r=e/d3, lc=r%d2, j=r/d2;
            double acc = 0.0;
            for (int i = 0; i < d1; i++) {
                cpx q1 = Qe(l1,i,j); if (q1.re==0 && q1.im==0) continue;
                for (int k = 0; k < d2; k++) {
                    cpx q2 = Qe(l2,k,lc); if (q2.re==0 && q2.im==0) continue;
                    int m1=i-l1, m2=k-l2, nn=l3+m1+m2;
                    if (nn < 0 || nn >= d3) continue;
                    cpx q3 = Qe(l3,nn,m); q3.im = -q3.im;
                    if (q3.re==0 && q3.im==0) continue;
                    cpx t = cmul(cmul(q1,q2), q3);
                    acc += t.re * su2(l1,l2,l3,m1,m2);
                }
            }
            o[PO[p]+e] = (float)acc;
        }
    }
}
}
static float h_cg_buf[615];

// combined prep: y<15 -> x transpose tile; y==15 -> W split
__global__ void __launch_bounds__(256, 4)
prep_all(const float* __restrict__ x, const float* __restrict__ W0,
         const float* __restrict__ W1, const float* __restrict__ W2) {
    __shared__ float tile[64][33];
    if (blockIdx.y < 15) {
        int b0 = blockIdx.x*64, j0 = blockIdx.y*32;
        int tx = threadIdx.x & 31, ty = threadIdx.x >> 5;
        #pragma unroll
        for (int r = 0; r < 8; r++)
            tile[ty + 8*r][tx] = x[(size_t)(b0 + ty + 8*r)*480 + j0 + tx];
        __syncthreads();
        #pragma unroll
        for (int r = 0; r < 4; r++) {
            int j = ty + 8*r;
            g_xT[(size_t)(j0+j)*BMAX + b0 + tx]      = tile[tx][j];
            g_xT[(size_t)(j0+j)*BMAX + b0 + 32 + tx] = tile[32 + tx][j];
        }
    } else {
        int idx = blockIdx.x;
        if (idx >= 60) return;
        int l3, ch;
        if (idx < 14)      { l3 = 0; ch = idx; }
        else if (idx < 38) { l3 = 1; ch = idx - 14; }
        else               { l3 = 2; ch = idx - 38; }
        const int Nt[3] = {128,64,32}, Tt[3] = {224,384,352};
        const float* W = l3==0 ? W0 : (l3==1 ? W1 : W2);
        int N = Nt[l3];
        float norm = 1.0f / sqrtf((float)Tt[l3]);
        for (int i = threadIdx.x; i < N*16; i += 256) {
            int v = i >> 4, kk = i & 15;
            int u = ch*16 + kk;
            g_w[l3][(ch*N + v)*16 + kk] = __float2half_rn(W[(size_t)u*N + v] * norm);
        }
    }
}

// ---------------- fused body (fp16 2-product, KUX-wide chunks) ----------------
template<int L3,int D3,int MULOUT,int TOT,int NA,int OBASE,int NRT,int NCT,int NC,int PITCH,int KUX>
__device__ __forceinline__ void
tp_body(const float* __restrict__ y, float* __restrict__ out, char* smc)
{
    constexpr int BY_UT = 2304;
    constexpr int BY_AS = 3840;
    constexpr int BY_AT = BY_AS + NA*256;
    constexpr int SUB   = KUX / 16;
    constexpr int PLANE = KUX*PITCH*2;
    constexpr int CPW    = 2;
    constexpr int W_COLS = NCT / CPW;
    constexpr int W_ROWS = 8 / W_COLS;
    constexpr int RPW    = NRT / W_ROWS;
    constexpr int SP  = MULOUT*D3 + 1;

    float* y_s = (float*)smc;
    int*   ut  = (int*)(smc + BY_UT);
    float* A_s = (float*)(smc + BY_AS);
    const int t = threadIdx.x, w = t >> 5, lane = t & 31;
    const int mg = lane >> 2, tg = lane & 3;
    const int lg = lane >> 3, lr = lane & 7;
    const int wc = w % W_COLS, wr = w / W_COLS;
    const int b0 = blockIdx.y * 64;
    const uint32_t smb = smem_u32(smc);

    for (int i = t; i < 64*9; i += 256) y_s[i] = y[(size_t)b0*9 + i];
    for (int u = t; u < TOT; u += 256) {
        int p = C_np[L3] - 1;
        while (u < C_uo[L3][p]) p--;
        int mm = u - C_uo[L3][p];
        ut[u] = (C_xb[L3][p] + mm*C_d1[L3][p]) | (C_ao[L3][p] << 9) | (C_d1[L3][p] << 16);
    }
    __syncthreads();

    // A = CG x y  (A_s[e*64+b])
    for (int it2 = t; it2 < NA*64; it2 += 256) {
        int e = it2 >> 6, b = it2 & 63;
        int p = C_np[L3] - 1;
        while (e < C_ao[L3][p]) p--;
        int loc = e - C_ao[L3][p];
        int i = loc / D3, k = loc - i*D3;
        int d2 = C_d2[L3][p];
        const float* cg = &g_cg[C_cgo[L3][p] + i*d2*D3 + k];
        const float* yb = &y_s[b*9 + C_yo[L3][p]];
        float s = 0.f;
        for (int jj = 0; jj < d2; jj++) s += cg[jj*D3] * yb[jj];
        A_s[e*64 + b] = s;
    }
    __syncthreads();

    const int ulp = t >> 4, bq = t & 15;
    const int laddr = ((lg >> 1)*8 + lr)*PITCH + (lg & 1)*8;

    float acc[RPW][CPW][4];
    #pragma unroll
    for (int j = 0; j < RPW; j++)
        #pragma unroll
        for (int i = 0; i < CPW; i++)
            #pragma unroll
            for (int q = 0; q < 4; q++) acc[j][i][q] = 0.f;

    uint32_t bcur[CPW][2*SUB], bnext[CPW][2*SUB];

    auto loadB = [&](int ch, uint32_t dst[][2*SUB]) {
        #pragma unroll
        for (int i = 0; i < CPW; i++) {
            int ct = wc*CPW + i;
            #pragma unroll
            for (int ks = 0; ks < SUB; ks++) {
                int be = ((ch*SUB + ks)*MULOUT + ct*8 + mg)*16 + 2*tg;
                dst[i][ks*2+0] = *(const uint32_t*)&g_w[L3][be];
                dst[i][ks*2+1] = *(const uint32_t*)&g_w[L3][be + 8];
            }
        }
    };

    // producer: z for u = c16*16 + ulp (sub-chunk), 4 batches -> fp16 hi/lo planes
    auto produce = [&](int c16, int nb, int sub) {
        int pk = ut[c16*16 + ulp];
        int xo = pk & 511, ao = (pk >> 9) & 127, d1 = pk >> 16;
        unsigned long long zx[D3], zy[D3];
        #pragma unroll
        for (int k = 0; k < D3; k++) { zx[k] = 0ULL; zy[k] = 0ULL; }
        for (int i = 0; i < d1; i++) {
            ulonglong2 xv = *(const ulonglong2*)&g_xT[(size_t)(xo+i)*BMAX + b0 + bq*4];
            #pragma unroll
            for (int k = 0; k < D3; k++) {
                ulonglong2 a2 = *(const ulonglong2*)&A_s[(ao + i*D3 + k)*64 + bq*4];
                zx[k] = ffma2(a2.x, xv.x, zx[k]);
                zy[k] = ffma2(a2.y, xv.y, zy[k]);
            }
        }
        #pragma unroll
        for (int k = 0; k < D3; k++) {
            float v0, v1, v2, v3;
            unpack2(zx[k], v0, v1);
            unpack2(zy[k], v2, v3);
            __half2 h01 = __floats2half2_rn(v0, v1);
            __half2 h23 = __floats2half2_rn(v2, v3);
            float2 f01 = __half22float2(h01);
            float2 f23 = __half22float2(h23);
            __half2 l01 = __floats2half2_rn(v0 - f01.x, v1 - f01.y);
            __half2 l23 = __floats2half2_rn(v2 - f23.x, v3 - f23.y);
            uint32_t off = (uint32_t)((sub*16 + ulp)*PITCH + k*64 + bq*4)*2;
            *(uint2*)(smc + BY_AT + (nb*2 + 0)*PLANE + off) =
                make_uint2(*(uint32_t*)&h01, *(uint32_t*)&h23);
            *(uint2*)(smc + BY_AT + (nb*2 + 1)*PLANE + off) =
                make_uint2(*(uint32_t*)&l01, *(uint32_t*)&l23);
        }
    };

    loadB(0, bcur);
    #pragma unroll
    for (int s = 0; s < SUB; s++) produce(s, 0, s);
    __syncthreads();

    for (int ch = 0; ch < NC; ch++) {
        int buf = ch & 1;
        if (ch + 1 < NC) {
            loadB(ch + 1, bnext);
            #pragma unroll
            for (int s = 0; s < SUB; s++) produce((ch + 1)*SUB + s, buf ^ 1, s);
        }

        #pragma unroll
        for (int j = 0; j < RPW; j++) {
            int rt = wr + W_ROWS*j;
            #pragma unroll
            for (int ks = 0; ks < SUB; ks++) {
                uint32_t ah0,ah1,ah2,ah3, al0,al1,al2,al3;
                uint32_t abase = smb + BY_AT + (buf*2)*PLANE
                               + (uint32_t)(laddr + ks*16*PITCH + rt*16)*2;
                ldsm4t(ah0, ah1, ah2, ah3, abase);
                ldsm4t(al0, al1, al2, al3, abase + PLANE);
                #pragma unroll
                for (int i = 0; i < CPW; i++) {
                    mma_f16(acc[j][i], ah0, ah1, ah2, ah3, bcur[i][ks*2], bcur[i][ks*2+1]);
                    mma_f16(acc[j][i], al0, al1, al2, al3, bcur[i][ks*2], bcur[i][ks*2+1]);
                }
            }
        }
        __syncthreads();
        if (ch + 1 < NC) {
            #pragma unroll
            for (int i = 0; i < CPW; i++)
                #pragma unroll
                for (int q = 0; q < 2*SUB; q++) bcur[i][q] = bnext[i][q];
        }
    }

    // epilogue
    float* out_s = (float*)smc;
    #pragma unroll
    for (int j = 0; j < RPW; j++) {
        int r0 = (wr + W_ROWS*j)*16 + mg;
        #pragma unroll
        for (int i = 0; i < CPW; i++) {
            int n0 = (wc*CPW + i)*8 + 2*tg;
            #pragma unroll
            for (int hrow = 0; hrow < 2; hrow++) {
                int m = r0 + hrow*8;
                int k3 = m >> 6, b = m & 63;
                out_s[b*SP + n0*D3 + k3]       = acc[j][i][hrow*2 + 0];
                out_s[b*SP + (n0 + 1)*D3 + k3] = acc[j][i][hrow*2 + 1];
            }
        }
    }
    __syncthreads();
    constexpr int MD3 = MULOUT*D3;
    for (int i = t; i < 64*MD3; i += 256) {
        int b = i / MD3, j = i - b*MD3;
        out[(size_t)(b0 + b)*480 + OBASE + j] = out_s[b*SP + j];
    }
}

__global__ void __launch_bounds__(256, 2)
tp_fused(const float* __restrict__ y, float* __restrict__ out)
{
    extern __shared__ char smc[];
    if (blockIdx.x == 0)      tp_body<0,1,128,224,  9,  0, 4,16, 7, 72,32>(y, out, smc);
    else if (blockIdx.x == 1) tp_body<1,3, 64,384, 60,128,12, 8,12,200,32>(y, out, smc);
    else                      tp_body<2,5, 32,352,110,320,20, 4,22,328,16>(y, out, smc);
}

extern "C" void kernel_launch(void* const* d_in, const int* in_sizes, int n_in,
                              void* d_out, int out_size) {
    const float* x  = (const float*)d_in[0];
    const float* y  = (const float*)d_in[1];
    const float* W0 = (const float*)d_in[2];
    const float* W1 = (const float*)d_in[3];
    const float* W2 = (const float*)d_in[4];
    float* out = (float*)d_out;
    int B = in_sizes[0] / 480;

    hostcg::compute(h_cg_buf);
    cudaMemcpyToSymbolAsync(g_cg, h_cg_buf, 615*sizeof(float), 0,
                            cudaMemcpyHostToDevice, 0);

    // max over branches: l3=2: 3840 + 110*256 + 4*16*328*2 = 73984
    constexpr int SMEM_BYTES = 73984;
    cudaFuncSetAttribute((const void*)tp_fused,
                         cudaFuncAttributeMaxDynamicSharedMemorySize, SMEM_BYTES);

    prep_all<<<dim3(B/64, 16), 256>>>(x, W0, W1, W2);
    tp_fused<<<dim3(3, B/64), 256, SMEM_BYTES>>>(y, out);
}

// round 17
// speedup vs baseline: 1.0541x; 1.0541x over previous
#include <cuda_runtime.h>
#include <cuda_fp16.h>
#include <math.h>
#include <stdint.h>

#define BMAX 16384

__device__ __forceinline__ unsigned long long ffma2(unsigned long long a,
                                                    unsigned long long b,
                                                    unsigned long long c) {
    unsigned long long d;
    asm("fma.rn.f32x2 %0, %1, %2, %3;" : "=l"(d) : "l"(a), "l"(b), "l"(c));
    return d;
}
__device__ __forceinline__ void unpack2(unsigned long long v, float& lo, float& hi) {
    asm("mov.b64 {%0, %1}, %2;" : "=f"(lo), "=f"(hi) : "l"(v));
}
__device__ __forceinline__ uint32_t smem_u32(const void* p) {
    uint32_t a;
    asm("{ .reg .u64 t; cvta.to.shared.u64 t, %1; cvt.u32.u64 %0, t; }" : "=r"(a) : "l"(p));
    return a;
}
__device__ __forceinline__ void cpasync16(uint32_t dst, const void* src) {
    asm volatile("cp.async.cg.shared.global [%0], [%1], 16;" :: "r"(dst), "l"(src) : "memory");
}
#define CP_COMMIT() asm volatile("cp.async.commit_group;" ::: "memory")
#define CP_WAIT0()  asm volatile("cp.async.wait_group 0;" ::: "memory")

__device__ __forceinline__ void ldsm4t(uint32_t& r0, uint32_t& r1, uint32_t& r2,
                                       uint32_t& r3, uint32_t addr) {
    asm volatile("ldmatrix.sync.aligned.m8n8.x4.trans.shared.b16 {%0,%1,%2,%3}, [%4];"
                 : "=r"(r0), "=r"(r1), "=r"(r2), "=r"(r3) : "r"(addr));
}
__device__ __forceinline__ void mma_f16(float* c, uint32_t a0, uint32_t a1,
                                        uint32_t a2, uint32_t a3,
                                        uint32_t b0, uint32_t b1) {
    asm volatile("mma.sync.aligned.m16n8k16.row.col.f32.f16.f16.f32 "
                 "{%0,%1,%2,%3}, {%4,%5,%6,%7}, {%8,%9}, {%0,%1,%2,%3};"
                 : "+f"(c[0]), "+f"(c[1]), "+f"(c[2]), "+f"(c[3])
                 : "r"(a0), "r"(a1), "r"(a2), "r"(a3), "r"(b0), "r"(b1));
}

__device__ float g_xT[480 * BMAX];
__device__ float g_cg[615];
__device__ __half g_w[3][28672];   // fp16 W, [(c16*N+v)*16+kk], norm folded

__constant__ int C_np[3]     = {3,6,6};
__constant__ int C_d1[3][6]  = {{1,3,5,0,0,0},{1,3,3,3,5,5},{1,3,3,5,5,5}};
__constant__ int C_d2[3][6]  = {{1,3,5,0,0,0},{3,1,3,5,3,5},{5,3,5,1,3,5}};
__constant__ int C_xb[3][6]  = {{0,128,320,0,0,0},{0,128,128,128,320,320},{0,128,128,320,320,320}};
__constant__ int C_yo[3][6]  = {{0,1,4,0,0,0},{1,0,1,4,1,4},{4,1,4,0,1,4}};
__constant__ int C_cgo[3][6] = {{0,1,10,0,0,0},{35,44,53,80,125,170},{245,270,315,390,415,490}};
__constant__ int C_uo[3][6]  = {{0,128,192,0,0,0},{0,128,192,256,320,352},{0,128,192,256,288,320}};
__constant__ int C_ao[3][6]  = {{0,1,4,0,0,0},{0,3,12,21,30,45},{0,5,20,35,60,85}};

// ===== host-side CG (exact reference algorithm) =====
namespace hostcg {
struct cpx { double re, im; };
static inline cpx cmul(cpx a, cpx b) { return { a.re*b.re - a.im*b.im, a.re*b.im + a.im*b.re }; }
static const double F[9] = {1.,1.,2.,6.,24.,120.,720.,5040.,40320.};
static double su2(int j1,int j2,int j3,int m1,int m2) {
    int m3 = m1 + m2;
    double pref = sqrt((2.0*j3+1.0)*F[j1+j2-j3]*F[j1-j2+j3]*F[-j1+j2+j3]/F[j1+j2+j3+1]);
    pref *= sqrt(F[j3+m3]*F[j3-m3]*F[j1-m1]*F[j1+m1]*F[j2-m2]*F[j2+m2]);
    double s = 0.0;
    for (int v = 0; v <= j1+j2-j3; v++) {
        int a=j1+j2-j3-v, b=j1-m1-v, c=j2+m2-v, d=j3-j2+m1+v, e=j3-j1-m2+v;
        if (a<0||b<0||c<0||d<0||e<0) continue;
        double t = 1.0/(F[v]*F[a]*F[b]*F[c]*F[d]*F[e]);
        s += (v & 1) ? -t : t;
    }
    return pref * s;
}
static cpx Qe(int l, int row, int col) {
    const double R = 0.70710678118654752440;
    cpx q = {0.0, 0.0};
    int m = row - l;
    if (m < 0)      { if (col == 2*l-row) q.re = R; else if (col == row) q.im = -R; }
    else if (m == 0){ if (col == l) q.re = 1.0; }
    else { double s = (m&1)?-1.0:1.0;
           if (col == row) q.re = s*R; else if (col == 2*l-row) q.im = s*R; }
    if (l == 1)      { double t = q.re; q.re = q.im; q.im = -t; }
    else if (l == 2) { q.re = -q.re; q.im = -q.im; }
    return q;
}
static void compute(float* o) {
    static const int P1[15]={0,1,2,0,1,1,1,2,2,0,1,1,2,2,2};
    static const int P2[15]={0,1,2,1,0,1,2,1,2,2,1,2,0,1,2};
    static const int P3[15]={0,0,0,1,1,1,1,1,1,2,2,2,2,2,2};
    static const int PO[15]={0,1,10,35,44,53,80,125,170,245,270,315,390,415,490};
    for (int p = 0; p < 15; p++) {
        int l1=P1[p], l2=P2[p], l3=P3[p], d1=2*l1+1, d2=2*l2+1, d3=2*l3+1;
        for (int e = 0; e < d1*d2*d3; e++) {
            int m=e%d3, r=e/d3, lc=r%d2, j=r/d2;
            double acc = 0.0;
            for (int i = 0; i < d1; i++) {
                cpx q1 = Qe(l1,i,j); if (q1.re==0 && q1.im==0) continue;
                for (int k = 0; k < d2; k++) {
                    cpx q2 = Qe(l2,k,lc); if (q2.re==0 && q2.im==0) continue;
                    int m1=i-l1, m2=k-l2, nn=l3+m1+m2;
                    if (nn < 0 || nn >= d3) continue;
                    cpx q3 = Qe(l3,nn,m); q3.im = -q3.im;
                    if (q3.re==0 && q3.im==0) continue;
                    cpx t = cmul(cmul(q1,q2), q3);
                    acc += t.re * su2(l1,l2,l3,m1,m2);
                }
            }
            o[PO[p]+e] = (float)acc;
        }
    }
}
}
static float h_cg_buf[615];

// combined prep: y<15 -> x transpose tile; y==15 -> W split
__global__ void __launch_bounds__(256, 4)
prep_all(const float* __restrict__ x, const float* __restrict__ W0,
         const float* __restrict__ W1, const float* __restrict__ W2) {
    __shared__ float tile[64][33];
    if (blockIdx.y < 15) {
        int b0 = blockIdx.x*64, j0 = blockIdx.y*32;
        int tx = threadIdx.x & 31, ty = threadIdx.x >> 5;
        #pragma unroll
        for (int r = 0; r < 8; r++)
            tile[ty + 8*r][tx] = x[(size_t)(b0 + ty + 8*r)*480 + j0 + tx];
        __syncthreads();
        #pragma unroll
        for (int r = 0; r < 4; r++) {
            int j = ty + 8*r;
            g_xT[(size_t)(j0+j)*BMAX + b0 + tx]      = tile[tx][j];
            g_xT[(size_t)(j0+j)*BMAX + b0 + 32 + tx] = tile[32 + tx][j];
        }
    } else {
        int idx = blockIdx.x;
        if (idx >= 60) return;
        int l3, ch;
        if (idx < 14)      { l3 = 0; ch = idx; }
        else if (idx < 38) { l3 = 1; ch = idx - 14; }
        else               { l3 = 2; ch = idx - 38; }
        const int Nt[3] = {128,64,32}, Tt[3] = {224,384,352};
        const float* W = l3==0 ? W0 : (l3==1 ? W1 : W2);
        int N = Nt[l3];
        float norm = 1.0f / sqrtf((float)Tt[l3]);
        for (int i = threadIdx.x; i < N*16; i += 256) {
            int v = i >> 4, kk = i & 15;
            int u = ch*16 + kk;
            g_w[l3][(ch*N + v)*16 + kk] = __float2half_rn(W[(size_t)u*N + v] * norm);
        }
    }
}

// ---------------- fused body (fp16 2-product, KUX chunks, cp.async x-staging) ----------------
template<int L3,int D3,int MULOUT,int TOT,int NA,int OBASE,int NRT,int NCT,int NC,int PITCH,int KUX>
__device__ __forceinline__ void
tp_body(const float* __restrict__ y, float* __restrict__ out, char* smc)
{
    constexpr int BY_UT = 2304;
    constexpr int BY_AS = 3840;
    constexpr int BY_AT = BY_AS + NA*256;
    constexpr int SUB   = KUX / 16;
    constexpr int PLANE = KUX*PITCH*2;
    constexpr int BY_XS = BY_AT + 4*PLANE;          // x stage: SUB*16 u x 5 rows x 64 b
    constexpr int CPW    = 2;
    constexpr int W_COLS = NCT / CPW;
    constexpr int W_ROWS = 8 / W_COLS;
    constexpr int RPW    = NRT / W_ROWS;
    constexpr int SP  = MULOUT*D3 + 1;

    float* y_s = (float*)smc;
    int*   ut  = (int*)(smc + BY_UT);
    float* A_s = (float*)(smc + BY_AS);
    float* xs  = (float*)(smc + BY_XS);
    const int t = threadIdx.x, w = t >> 5, lane = t & 31;
    const int mg = lane >> 2, tg = lane & 3;
    const int lg = lane >> 3, lr = lane & 7;
    const int wc = w % W_COLS, wr = w / W_COLS;
    const int b0 = blockIdx.x * 64;
    const uint32_t smb = smem_u32(smc);

    for (int i = t; i < 64*9; i += 256) y_s[i] = y[(size_t)b0*9 + i];
    for (int u = t; u < TOT; u += 256) {
        int p = C_np[L3] - 1;
        while (u < C_uo[L3][p]) p--;
        int mm = u - C_uo[L3][p];
        ut[u] = (C_xb[L3][p] + mm*C_d1[L3][p]) | (C_ao[L3][p] << 9) | (C_d1[L3][p] << 16);
    }
    __syncthreads();

    // A = CG x y  (A_s[e*64+b])
    for (int it2 = t; it2 < NA*64; it2 += 256) {
        int e = it2 >> 6, b = it2 & 63;
        int p = C_np[L3] - 1;
        while (e < C_ao[L3][p]) p--;
        int loc = e - C_ao[L3][p];
        int i = loc / D3, k = loc - i*D3;
        int d2 = C_d2[L3][p];
        const float* cg = &g_cg[C_cgo[L3][p] + i*d2*D3 + k];
        const float* yb = &y_s[b*9 + C_yo[L3][p]];
        float s = 0.f;
        for (int jj = 0; jj < d2; jj++) s += cg[jj*D3] * yb[jj];
        A_s[e*64 + b] = s;
    }
    __syncthreads();

    const int ulp = t >> 4, bq = t & 15;
    const int laddr = ((lg >> 1)*8 + lr)*PITCH + (lg & 1)*8;

    float acc[RPW][CPW][4];
    #pragma unroll
    for (int j = 0; j < RPW; j++)
        #pragma unroll
        for (int i = 0; i < CPW; i++)
            #pragma unroll
            for (int q = 0; q < 4; q++) acc[j][i][q] = 0.f;

    uint32_t bcur[CPW][2*SUB], bnext[CPW][2*SUB];

    auto loadB = [&](int ch, uint32_t dst[][2*SUB]) {
        #pragma unroll
        for (int i = 0; i < CPW; i++) {
            int ct = wc*CPW + i;
            #pragma unroll
            for (int ks = 0; ks < SUB; ks++) {
                int be = ((ch*SUB + ks)*MULOUT + ct*8 + mg)*16 + 2*tg;
                dst[i][ks*2+0] = *(const uint32_t*)&g_w[L3][be];
                dst[i][ks*2+1] = *(const uint32_t*)&g_w[L3][be + 8];
            }
        }
    };

    // cp.async: copy the 5 x rows / 16B segment this thread will consume (all subs)
    auto issueX = [&](int ch) {
        #pragma unroll
        for (int s = 0; s < SUB; s++) {
            int xo = ut[(ch*SUB + s)*16 + ulp] & 511;
            uint32_t dbase = smb + BY_XS + (uint32_t)(((s*16 + ulp)*5)*64 + bq*4)*4;
            const float* sbase = &g_xT[(size_t)xo*BMAX + b0 + bq*4];
            #pragma unroll
            for (int i = 0; i < 5; i++)
                cpasync16(dbase + i*64*4, sbase + (size_t)i*BMAX);
        }
        CP_COMMIT();
    };

    // producer: z from staged x (LDS) -> fp16 hi/lo planes
    auto produce = [&](int c16, int nb, int sub) {
        int pk = ut[c16*16 + ulp];
        int ao = (pk >> 9) & 127, d1 = pk >> 16;
        const float* xsp = xs + ((sub*16 + ulp)*5)*64 + bq*4;
        unsigned long long zx[D3], zy[D3];
        #pragma unroll
        for (int k = 0; k < D3; k++) { zx[k] = 0ULL; zy[k] = 0ULL; }
        for (int i = 0; i < d1; i++) {
            ulonglong2 xv = *(const ulonglong2*)(xsp + i*64);
            #pragma unroll
            for (int k = 0; k < D3; k++) {
                ulonglong2 a2 = *(const ulonglong2*)&A_s[(ao + i*D3 + k)*64 + bq*4];
                zx[k] = ffma2(a2.x, xv.x, zx[k]);
                zy[k] = ffma2(a2.y, xv.y, zy[k]);
            }
        }
        #pragma unroll
        for (int k = 0; k < D3; k++) {
            float v0, v1, v2, v3;
            unpack2(zx[k], v0, v1);
            unpack2(zy[k], v2, v3);
            __half2 h01 = __floats2half2_rn(v0, v1);
            __half2 h23 = __floats2half2_rn(v2, v3);
            float2 f01 = __half22float2(h01);
            float2 f23 = __half22float2(h23);
            __half2 l01 = __floats2half2_rn(v0 - f01.x, v1 - f01.y);
            __half2 l23 = __floats2half2_rn(v2 - f23.x, v3 - f23.y);
            uint32_t off = (uint32_t)((sub*16 + ulp)*PITCH + k*64 + bq*4)*2;
            *(uint2*)(smc + BY_AT + (nb*2 + 0)*PLANE + off) =
                make_uint2(*(uint32_t*)&h01, *(uint32_t*)&h23);
            *(uint2*)(smc + BY_AT + (nb*2 + 1)*PLANE + off) =
                make_uint2(*(uint32_t*)&l01, *(uint32_t*)&l23);
        }
    };

    loadB(0, bcur);
    issueX(0);
    CP_WAIT0();
    #pragma unroll
    for (int s = 0; s < SUB; s++) produce(s, 0, s);
    __syncthreads();

    for (int ch = 0; ch < NC; ch++) {
        int buf = ch & 1;
        if (ch + 1 < NC) { issueX(ch + 1); loadB(ch + 1, bnext); }

        #pragma unroll
        for (int j = 0; j < RPW; j++) {
            int rt = wr + W_ROWS*j;
            #pragma unroll
            for (int ks = 0; ks < SUB; ks++) {
                uint32_t ah0,ah1,ah2,ah3, al0,al1,al2,al3;
                uint32_t abase = smb + BY_AT + (buf*2)*PLANE
                               + (uint32_t)(laddr + ks*16*PITCH + rt*16)*2;
                ldsm4t(ah0, ah1, ah2, ah3, abase);
                ldsm4t(al0, al1, al2, al3, abase + PLANE);
                #pragma unroll
                for (int i = 0; i < CPW; i++) {
                    mma_f16(acc[j][i], ah0, ah1, ah2, ah3, bcur[i][ks*2], bcur[i][ks*2+1]);
                    mma_f16(acc[j][i], al0, al1, al2, al3, bcur[i][ks*2], bcur[i][ks*2+1]);
                }
            }
        }
        if (ch + 1 < NC) {
            CP_WAIT0();
            #pragma unroll
            for (int s = 0; s < SUB; s++) produce((ch + 1)*SUB + s, buf ^ 1, s);
        }
        __syncthreads();
        if (ch + 1 < NC) {
            #pragma unroll
            for (int i = 0; i < CPW; i++)
                #pragma unroll
                for (int q = 0; q < 2*SUB; q++) bcur[i][q] = bnext[i][q];
        }
    }

    // epilogue
    float* out_s = (float*)smc;
    #pragma unroll
    for (int j = 0; j < RPW; j++) {
        int r0 = (wr + W_ROWS*j)*16 + mg;
        #pragma unroll
        for (int i = 0; i < CPW; i++) {
            int n0 = (wc*CPW + i)*8 + 2*tg;
            #pragma unroll
            for (int hrow = 0; hrow < 2; hrow++) {
                int m = r0 + hrow*8;
                int k3 = m >> 6, b = m & 63;
                out_s[b*SP + n0*D3 + k3]       = acc[j][i][hrow*2 + 0];
                out_s[b*SP + (n0 + 1)*D3 + k3] = acc[j][i][hrow*2 + 1];
            }
        }
    }
    __syncthreads();
    constexpr int MD3 = MULOUT*D3;
    for (int i = t; i < 64*MD3; i += 256) {
        int b = i / MD3, j = i - b*MD3;
        out[(size_t)(b0 + b)*480 + OBASE + j] = out_s[b*SP + j];
    }
}

__global__ void __launch_bounds__(256, 2)
tp_fused(const float* __restrict__ y, float* __restrict__ out)
{
    extern __shared__ char smc[];
    if (blockIdx.y == 0)      tp_body<0,1,128,224,  9,  0, 4,16, 7, 72,32>(y, out, smc);
    else if (blockIdx.y == 1) tp_body<1,3, 64,384, 60,128,12, 8,12,200,32>(y, out, smc);
    else                      tp_body<2,5, 32,352,110,320,20, 4,22,328,16>(y, out, smc);
}

extern "C" void kernel_launch(void* const* d_in, const int* in_sizes, int n_in,
                              void* d_out, int out_size) {
    const float* x  = (const float*)d_in[0];
    const float* y  = (const float*)d_in[1];
    const float* W0 = (const float*)d_in[2];
    const float* W1 = (const float*)d_in[3];
    const float* W2 = (const float*)d_in[4];
    float* out = (float*)d_out;
    int B = in_sizes[0] / 480;

    hostcg::compute(h_cg_buf);
    cudaMemcpyToSymbolAsync(g_cg, h_cg_buf, 615*sizeof(float), 0,
                            cudaMemcpyHostToDevice, 0);

    // max over branches: l3=1: 3840 + 60*256 + 4*32*200*2 + 2*16*5*64*4 = 111360
    constexpr int SMEM_BYTES = 111360;
    cudaFuncSetAttribute((const void*)tp_fused,
                         cudaFuncAttributeMaxDynamicSharedMemorySize, SMEM_BYTES);

    prep_all<<<dim3(B/64, 16), 256>>>(x, W0, W1, W2);
    tp_fused<<<dim3(B/64, 3), 256, SMEM_BYTES>>>(y, out);
}